// round 14
// baseline (speedup 1.0000x reference)
#include <cuda_runtime.h>
#include <cuda_bf16.h>
#include <cstdint>

// AggregationLayer: y[s] = mean over edges e with segment_ids[e]==s of
//                   layer_values[gather_idx[e], :]
// d_in[0]: layer_values f32 [N_SRC*64]
// d_in[1]: gather_idx   i32 [E]
// d_in[2]: segment_ids  i32 [E] (sorted ascending)
// out: f32 [n_seg*64]

#define D 64
#define SEGS_PER_BLOCK 64
#define SEGS_PER_WARP 8
#define IDX_CAP 4096

// CSR row offsets scratch (n_seg <= 1M supported). +1 terminator.
__device__ int g_begin[1048577];

// Boundary finder: 8 edges per thread via 2x int4; prev via shfl.
__global__ void __launch_bounds__(256)
build_csr_kernel(const int* __restrict__ segs, int E, int n_seg)
{
    const int e8 = (blockIdx.x * blockDim.x + threadIdx.x) * 8;

    int c[8];
    const int rem = (e8 < E) ? (E - e8) : 0;
    if (rem >= 8) {
        int4 a = *reinterpret_cast<const int4*>(segs + e8);
        int4 b = *reinterpret_cast<const int4*>(segs + e8 + 4);
        c[0]=a.x; c[1]=a.y; c[2]=a.z; c[3]=a.w;
        c[4]=b.x; c[5]=b.y; c[6]=b.z; c[7]=b.w;
    } else if (rem > 0) {
        int last = 0;
        #pragma unroll
        for (int k = 0; k < 8; ++k) {
            if (k < rem) { last = __ldg(segs + e8 + k); }
            c[k] = last;
        }
    } else {
        #pragma unroll
        for (int k = 0; k < 8; ++k) c[k] = 0;
    }

    // prev = segs[e8-1]: last element of the neighbor lane's chunk
    int prev = __shfl_up_sync(0xffffffffu, c[7], 1);
    const int lane = threadIdx.x & 31;
    if (lane == 0) {
        prev = (e8 == 0) ? -1 : ((e8 <= E) ? __ldg(segs + e8 - 1) : 0);
    }
    if (rem == 0) return;

    const int kmax = (rem < 8) ? rem : 8;
    #pragma unroll
    for (int k = 0; k < 8; ++k) {
        if (k < kmax) {
            for (int t = prev + 1; t <= c[k]; ++t) g_begin[t] = e8 + k;
            prev = c[k];
        }
    }
    if (e8 + kmax >= E) {
        for (int t = prev + 1; t <= n_seg; ++t) g_begin[t] = E;
    }
}

// Block handles 64 consecutive segments (8 per warp, serial). One coalesced
// smem staging of offsets + the block's full edge-index span. Row-load phase
// uses predicated full-width 8-bursts: no serialized remainder loads.
__global__ void __launch_bounds__(256)
agg_seg_mean_kernel(const float* __restrict__ vals,
                    const int*   __restrict__ gidx,
                    float*       __restrict__ out,
                    int n_seg)
{
    __shared__ int s_begin[SEGS_PER_BLOCK + 1];
    __shared__ int s_idx[IDX_CAP];

    const int tid = threadIdx.x;
    const int b0  = blockIdx.x * SEGS_PER_BLOCK;

    if (tid <= SEGS_PER_BLOCK) {
        int s = b0 + tid;
        if (s > n_seg) s = n_seg;
        s_begin[tid] = g_begin[s];
    }
    __syncthreads();

    const int base0 = s_begin[0];
    const int span  = s_begin[SEGS_PER_BLOCK] - base0;
    const bool cached = (span <= IDX_CAP);

    if (cached) {
        for (int i = tid; i < span; i += 256)
            s_idx[i] = __ldcs(gidx + base0 + i);
    }
    __syncthreads();

    const int w    = tid >> 5;
    const int lane = tid & 31;

    const float2* __restrict__ vals2 = reinterpret_cast<const float2*>(vals);

    #pragma unroll 1
    for (int ss = 0; ss < SEGS_PER_WARP; ++ss) {
        const int sl = w * SEGS_PER_WARP + ss;   // local segment index
        const int s  = b0 + sl;
        if (s >= n_seg) break;

        const int begin = s_begin[sl];
        const int end   = s_begin[sl + 1];
        const int cnt   = end - begin;

        float ax = 0.f, ay = 0.f;

        if (cached) {
            const int j0   = begin - base0;
            const int jend = end - base0;
            // predicated full-width bursts: every iteration issues 8
            // independent loads; out-of-range slots re-load edge j0
            // (L1 hit) with weight 0.
            for (int j = j0; j < jend; j += 8) {
                #pragma unroll
                for (int k = 0; k < 8; ++k) {
                    const int  jj = j + k;
                    const bool ok = (jj < jend);
                    const int  r  = s_idx[ok ? jj : j0];
                    const float w8 = ok ? 1.0f : 0.0f;
                    float2 v = __ldg(vals2 + (size_t)r * (D/2) + lane);
                    ax = fmaf(w8, v.x, ax);
                    ay = fmaf(w8, v.y, ay);
                }
            }
        } else {
            // rare fallback: block's edge span exceeded the smem cache
            for (int e = begin; e < end; e += 8) {
                #pragma unroll
                for (int k = 0; k < 8; ++k) {
                    const int  ee = e + k;
                    const bool ok = (ee < end);
                    const int  r  = __ldg(gidx + (ok ? ee : begin));
                    const float w8 = ok ? 1.0f : 0.0f;
                    float2 v = __ldg(vals2 + (size_t)r * (D/2) + lane);
                    ax = fmaf(w8, v.x, ax);
                    ay = fmaf(w8, v.y, ay);
                }
            }
        }

        const float inv = 1.0f / (float)max(cnt, 1);
        float2 res;
        res.x = ax * inv;
        res.y = ay * inv;
        __stcs(reinterpret_cast<float2*>(out) + (size_t)s * (D/2) + lane, res);
    }
}

extern "C" void kernel_launch(void* const* d_in, const int* in_sizes, int n_in,
                              void* d_out, int out_size)
{
    const float* vals = (const float*)d_in[0];
    const int*   gidx = (const int*)d_in[1];
    const int*   segs = (const int*)d_in[2];
    float*       out  = (float*)d_out;

    const int E     = in_sizes[1];
    const int n_seg = out_size / D;

    // 1) build CSR offsets (8 edges/thread, single-pass read)
    {
        const int threads = 256;
        const int elems_per_block = threads * 8;
        const int blocks = (E + elems_per_block - 1) / elems_per_block;
        build_csr_kernel<<<blocks, threads>>>(segs, E, n_seg);
    }
    // 2) block-staged (64 segs) warp-per-segment gather + mean
    {
        const int threads = 256;
        const int blocks = (n_seg + SEGS_PER_BLOCK - 1) / SEGS_PER_BLOCK;
        agg_seg_mean_kernel<<<blocks, threads>>>(vals, gidx, out, n_seg);
    }
}

// round 15
// speedup vs baseline: 1.1173x; 1.1173x over previous
#include <cuda_runtime.h>
#include <cuda_bf16.h>
#include <cstdint>

// AggregationLayer: y[s] = mean over edges e with segment_ids[e]==s of
//                   layer_values[gather_idx[e], :]
// d_in[0]: layer_values f32 [N_SRC*64]
// d_in[1]: gather_idx   i32 [E]
// d_in[2]: segment_ids  i32 [E] (sorted ascending)
// out: f32 [n_seg*64]

#define D 64
#define SEGS_PER_BLOCK 32
#define SEGS_PER_WARP 4
#define IDX_CAP 2048

// CSR row offsets scratch (n_seg <= 1M supported). +1 terminator.
__device__ int g_begin[1048577];

// Boundary finder: 16 edges per thread via 4x int4; prev via shfl.
__global__ void __launch_bounds__(256)
build_csr_kernel(const int* __restrict__ segs, int E, int n_seg)
{
    const int e0 = (blockIdx.x * blockDim.x + threadIdx.x) * 16;

    int c[16];
    const int rem = (e0 < E) ? (E - e0) : 0;
    if (rem >= 16) {
        #pragma unroll
        for (int q = 0; q < 4; ++q) {
            int4 a = *reinterpret_cast<const int4*>(segs + e0 + 4 * q);
            c[4*q+0] = a.x; c[4*q+1] = a.y; c[4*q+2] = a.z; c[4*q+3] = a.w;
        }
    } else if (rem > 0) {
        int last = 0;
        #pragma unroll
        for (int k = 0; k < 16; ++k) {
            if (k < rem) { last = __ldg(segs + e0 + k); }
            c[k] = last;
        }
    } else {
        #pragma unroll
        for (int k = 0; k < 16; ++k) c[k] = 0;
    }

    // prev = segs[e0-1]: last element of the neighbor lane's chunk
    int prev = __shfl_up_sync(0xffffffffu, c[15], 1);
    const int lane = threadIdx.x & 31;
    if (lane == 0) {
        prev = (e0 == 0) ? -1 : ((e0 <= E) ? __ldg(segs + e0 - 1) : 0);
    }
    if (rem == 0) return;

    const int kmax = (rem < 16) ? rem : 16;
    #pragma unroll
    for (int k = 0; k < 16; ++k) {
        if (k < kmax) {
            for (int t = prev + 1; t <= c[k]; ++t) g_begin[t] = e0 + k;
            prev = c[k];
        }
    }
    if (e0 + kmax >= E) {
        for (int t = prev + 1; t <= n_seg; ++t) g_begin[t] = E;
    }
}

// Block handles 32 consecutive segments (4 per warp). One coalesced smem
// staging of offsets + the block's full edge-index span. Row-load phase uses
// predicated full-width 8-bursts: no serialized remainder loads.
__global__ void __launch_bounds__(256)
agg_seg_mean_kernel(const float* __restrict__ vals,
                    const int*   __restrict__ gidx,
                    float*       __restrict__ out,
                    int n_seg)
{
    __shared__ int s_begin[SEGS_PER_BLOCK + 1];
    __shared__ int s_idx[IDX_CAP];

    const int tid = threadIdx.x;
    const int b0  = blockIdx.x * SEGS_PER_BLOCK;

    if (tid <= SEGS_PER_BLOCK) {
        int s = b0 + tid;
        if (s > n_seg) s = n_seg;
        s_begin[tid] = g_begin[s];
    }
    __syncthreads();

    const int base0 = s_begin[0];
    const int span  = s_begin[SEGS_PER_BLOCK] - base0;
    const bool cached = (span <= IDX_CAP);

    if (cached) {
        for (int i = tid; i < span; i += 256)
            s_idx[i] = __ldcs(gidx + base0 + i);   // streaming: keep L2 for table
    }
    __syncthreads();

    const int w    = tid >> 5;
    const int lane = tid & 31;

    const float2* __restrict__ vals2 = reinterpret_cast<const float2*>(vals);

    #pragma unroll
    for (int ss = 0; ss < SEGS_PER_WARP; ++ss) {
        const int sl = w * SEGS_PER_WARP + ss;   // local segment index
        const int s  = b0 + sl;
        if (s >= n_seg) break;

        const int begin = s_begin[sl];
        const int end   = s_begin[sl + 1];
        const int cnt   = end - begin;

        float ax = 0.f, ay = 0.f;

        if (cached) {
            const int j0   = begin - base0;
            const int jend = end - base0;
            // predicated full-width bursts: every iteration issues 8
            // independent loads; out-of-range slots re-load edge j0
            // (L1 hit) with weight 0.
            for (int j = j0; j < jend; j += 8) {
                #pragma unroll
                for (int k = 0; k < 8; ++k) {
                    const int  jj = j + k;
                    const bool ok = (jj < jend);
                    const int  r  = s_idx[ok ? jj : j0];
                    const float w8 = ok ? 1.0f : 0.0f;
                    float2 v = __ldg(vals2 + (size_t)r * (D/2) + lane);
                    ax = fmaf(w8, v.x, ax);
                    ay = fmaf(w8, v.y, ay);
                }
            }
        } else {
            // rare fallback: block's edge span exceeded the smem cache
            for (int e = begin; e < end; e += 8) {
                #pragma unroll
                for (int k = 0; k < 8; ++k) {
                    const int  ee = e + k;
                    const bool ok = (ee < end);
                    const int  r  = __ldg(gidx + (ok ? ee : begin));
                    const float w8 = ok ? 1.0f : 0.0f;
                    float2 v = __ldg(vals2 + (size_t)r * (D/2) + lane);
                    ax = fmaf(w8, v.x, ax);
                    ay = fmaf(w8, v.y, ay);
                }
            }
        }

        const float inv = 1.0f / (float)max(cnt, 1);
        float2 res;
        res.x = ax * inv;
        res.y = ay * inv;
        // streaming store: output never re-read; keep L2 for the table
        __stcs(reinterpret_cast<float2*>(out) + (size_t)s * (D/2) + lane, res);
    }
}

extern "C" void kernel_launch(void* const* d_in, const int* in_sizes, int n_in,
                              void* d_out, int out_size)
{
    const float* vals = (const float*)d_in[0];
    const int*   gidx = (const int*)d_in[1];
    const int*   segs = (const int*)d_in[2];
    float*       out  = (float*)d_out;

    const int E     = in_sizes[1];
    const int n_seg = out_size / D;

    // 1) build CSR offsets (16 edges/thread, single-pass read)
    {
        const int threads = 256;
        const int elems_per_block = threads * 16;
        const int blocks = (E + elems_per_block - 1) / elems_per_block;
        build_csr_kernel<<<blocks, threads>>>(segs, E, n_seg);
    }
    // 2) block-staged (32 segs) warp-per-segment gather + mean
    {
        const int threads = 256;
        const int blocks = (n_seg + SEGS_PER_BLOCK - 1) / SEGS_PER_BLOCK;
        agg_seg_mean_kernel<<<blocks, threads>>>(vals, gidx, out, n_seg);
    }
}

// round 16
// speedup vs baseline: 1.1226x; 1.0048x over previous
#include <cuda_runtime.h>
#include <cuda_bf16.h>
#include <cstdint>

// AggregationLayer: y[s] = mean over edges e with segment_ids[e]==s of
//                   layer_values[gather_idx[e], :]
// d_in[0]: layer_values f32 [N_SRC*64]
// d_in[1]: gather_idx   i32 [E]
// d_in[2]: segment_ids  i32 [E] (sorted ascending)
// out: f32 [n_seg*64]

#define D 64
#define SEGS_PER_BLOCK 32
#define SEGS_PER_WARP 4
#define IDX_CAP 2048

// CSR row offsets scratch (n_seg <= 1M supported). +1 terminator.
__device__ int g_begin[1048577];

// Boundary finder: 16 edges per thread via 4x int4; prev via shfl.
__global__ void __launch_bounds__(256)
build_csr_kernel(const int* __restrict__ segs, int E, int n_seg)
{
    const int e0 = (blockIdx.x * blockDim.x + threadIdx.x) * 16;

    int c[16];
    const int rem = (e0 < E) ? (E - e0) : 0;
    if (rem >= 16) {
        #pragma unroll
        for (int q = 0; q < 4; ++q) {
            int4 a = *reinterpret_cast<const int4*>(segs + e0 + 4 * q);
            c[4*q+0] = a.x; c[4*q+1] = a.y; c[4*q+2] = a.z; c[4*q+3] = a.w;
        }
    } else if (rem > 0) {
        int last = 0;
        #pragma unroll
        for (int k = 0; k < 16; ++k) {
            if (k < rem) { last = __ldg(segs + e0 + k); }
            c[k] = last;
        }
    } else {
        #pragma unroll
        for (int k = 0; k < 16; ++k) c[k] = 0;
    }

    // prev = segs[e0-1]: last element of the neighbor lane's chunk
    int prev = __shfl_up_sync(0xffffffffu, c[15], 1);
    const int lane = threadIdx.x & 31;
    if (lane == 0) {
        prev = (e0 == 0) ? -1 : ((e0 <= E) ? __ldg(segs + e0 - 1) : 0);
    }
    if (rem == 0) return;

    const int kmax = (rem < 16) ? rem : 16;
    #pragma unroll
    for (int k = 0; k < 16; ++k) {
        if (k < kmax) {
            for (int t = prev + 1; t <= c[k]; ++t) g_begin[t] = e0 + k;
            prev = c[k];
        }
    }
    if (e0 + kmax >= E) {
        for (int t = prev + 1; t <= n_seg; ++t) g_begin[t] = E;
    }
}

// Block handles 32 consecutive segments (4 per warp). One coalesced smem
// staging of offsets + the block's full edge-index span. Row-load phase uses
// predicated full-width 8-bursts: no serialized remainder loads.
__global__ void __launch_bounds__(256)
agg_seg_mean_kernel(const float* __restrict__ vals,
                    const int*   __restrict__ gidx,
                    float*       __restrict__ out,
                    int n_seg)
{
    __shared__ int s_begin[SEGS_PER_BLOCK + 1];
    __shared__ int s_idx[IDX_CAP];

    const int tid = threadIdx.x;
    const int b0  = blockIdx.x * SEGS_PER_BLOCK;

    if (tid <= SEGS_PER_BLOCK) {
        int s = b0 + tid;
        if (s > n_seg) s = n_seg;
        s_begin[tid] = g_begin[s];
    }
    __syncthreads();

    const int base0 = s_begin[0];
    const int span  = s_begin[SEGS_PER_BLOCK] - base0;
    const bool cached = (span <= IDX_CAP);

    if (cached) {
        for (int i = tid; i < span; i += 256)
            s_idx[i] = __ldcs(gidx + base0 + i);   // streaming: keep L2 for table
    }
    __syncthreads();

    const int w    = tid >> 5;
    const int lane = tid & 31;

    const float2* __restrict__ vals2 = reinterpret_cast<const float2*>(vals);

    #pragma unroll
    for (int ss = 0; ss < SEGS_PER_WARP; ++ss) {
        const int sl = w * SEGS_PER_WARP + ss;   // local segment index
        const int s  = b0 + sl;
        if (s >= n_seg) break;

        const int begin = s_begin[sl];
        const int end   = s_begin[sl + 1];
        const int cnt   = end - begin;

        float ax = 0.f, ay = 0.f;

        if (cached) {
            const int j0   = begin - base0;
            const int jend = end - base0;
            // predicated full-width bursts: every iteration issues 8
            // independent loads; out-of-range slots re-load edge j0
            // (L1 hit) with weight 0.
            for (int j = j0; j < jend; j += 8) {
                #pragma unroll
                for (int k = 0; k < 8; ++k) {
                    const int  jj = j + k;
                    const bool ok = (jj < jend);
                    const int  r  = s_idx[ok ? jj : j0];
                    const float w8 = ok ? 1.0f : 0.0f;
                    float2 v = __ldg(vals2 + (size_t)r * (D/2) + lane);
                    ax = fmaf(w8, v.x, ax);
                    ay = fmaf(w8, v.y, ay);
                }
            }
        } else {
            // rare fallback: block's edge span exceeded the smem cache
            for (int e = begin; e < end; e += 8) {
                #pragma unroll
                for (int k = 0; k < 8; ++k) {
                    const int  ee = e + k;
                    const bool ok = (ee < end);
                    const int  r  = __ldg(gidx + (ok ? ee : begin));
                    const float w8 = ok ? 1.0f : 0.0f;
                    float2 v = __ldg(vals2 + (size_t)r * (D/2) + lane);
                    ax = fmaf(w8, v.x, ax);
                    ay = fmaf(w8, v.y, ay);
                }
            }
        }

        const float inv = 1.0f / (float)max(cnt, 1);
        float2 res;
        res.x = ax * inv;
        res.y = ay * inv;
        // streaming store: output never re-read; keep L2 for the table
        __stcs(reinterpret_cast<float2*>(out) + (size_t)s * (D/2) + lane, res);
    }
}

extern "C" void kernel_launch(void* const* d_in, const int* in_sizes, int n_in,
                              void* d_out, int out_size)
{
    const float* vals = (const float*)d_in[0];
    const int*   gidx = (const int*)d_in[1];
    const int*   segs = (const int*)d_in[2];
    float*       out  = (float*)d_out;

    const int E     = in_sizes[1];
    const int n_seg = out_size / D;

    // 1) build CSR offsets (16 edges/thread, single-pass read)
    {
        const int threads = 256;
        const int elems_per_block = threads * 16;
        const int blocks = (E + elems_per_block - 1) / elems_per_block;
        build_csr_kernel<<<blocks, threads>>>(segs, E, n_seg);
    }
    // 2) block-staged (32 segs) warp-per-segment gather + mean
    {
        const int threads = 256;
        const int blocks = (n_seg + SEGS_PER_BLOCK - 1) / SEGS_PER_BLOCK;
        agg_seg_mean_kernel<<<blocks, threads>>>(vals, gidx, out, n_seg);
    }
}